// round 12
// baseline (speedup 1.0000x reference)
#include <cuda_runtime.h>
#include <cstdint>

#define BB 32768
#define DD 512
#define EE 10
#define HH 128
#define RH1 256
#define RH2 128

// ---- scratch (static __device__ globals: allocation-guard safe) ----
__device__ float g_hr1[(size_t)BB * RH1];          // router L1 out (tf32-rounded)
__device__ float g_xt[(size_t)BB * DD];            // tf32-rounded x
__device__ float g_wr1[(size_t)DD * RH1];          // tf32-rounded weights
__device__ float g_wr2[(size_t)RH1 * RH2];
__device__ float g_we1[(size_t)EE * DD * HH];
__device__ float g_we2[(size_t)EE * HH * HH];
__device__ int   g_cnt[BB / 128];                  // per-row-block completion count

__device__ __forceinline__ float tf32r(float f) {
    float r; asm("cvt.rna.tf32.f32 %0, %1;" : "=f"(r) : "f"(f)); return r;
}
__device__ __forceinline__ uint32_t s2u(const void* p) {
    uint32_t a;
    asm("{ .reg .u64 t; cvta.to.shared.u64 t, %1; cvt.u32.u64 %0, t; }" : "=r"(a) : "l"(p));
    return a;
}

// ---- smem geometry (floats). Conflict-free strides: 36%32=4, 136%32=8, 132%32=4.
#define A_STRIDE 36
#define B_STRIDE 136
#define A_STG (128 * A_STRIDE)             // 4608 floats
#define B_STG (32 * B_STRIDE)              // 4352 floats
#define STG_F (A_STG + B_STG)              // 8960 floats per stage
#define L2B_OFF (2 * STG_F)                // expert L2-B ring lives in stage 2
#define H1_STRIDE 132                      // h1 smem buffer stride (overlays stages 0-1)
#define MEGA_SMEM (3 * STG_F * 4)          // 107520 B -> still 2 CTAs/SM

#define CPA(dst, src) \
    asm volatile("cp.async.cg.shared.global [%0], [%1], 16;" :: "r"(dst), "l"(src) : "memory")
#define CPC() asm volatile("cp.async.commit_group;" ::: "memory")
#define CPW0() asm volatile("cp.async.wait_group 0;" ::: "memory")
#define CPW1() asm volatile("cp.async.wait_group 1;" ::: "memory")

#define MMA8(cc, a0, a1, a2, a3, b0, b1) \
    asm volatile("mma.sync.aligned.m16n8k8.row.col.f32.tf32.tf32.f32 " \
                 "{%0,%1,%2,%3}, {%4,%5,%6,%7}, {%8,%9}, {%0,%1,%2,%3};" \
                 : "+f"(cc[0]), "+f"(cc[1]), "+f"(cc[2]), "+f"(cc[3]) \
                 : "r"(a0), "r"(a1), "r"(a2), "r"(a3), "r"(b0), "r"(b1))

// One 32-k chunk of 128x128 CTA-tile MMA work. 8 warps (4m x 2n), warp tile
// 32x64 (mt=2, nt=8). AsU stride astride; BsU stride B_STRIDE.
__device__ __forceinline__ void mma_chunk(
    const uint32_t* __restrict__ AsU, int astride,
    const uint32_t* __restrict__ BsU,
    float (&c)[2][8][4], int warp_m, int warp_n, int grp, int tig)
{
#pragma unroll
    for (int ks = 0; ks < 4; ks++) {
        uint32_t a[2][4];
#pragma unroll
        for (int mt = 0; mt < 2; mt++) {
            const int rb = warp_m * 32 + mt * 16 + grp;
            const int kb = ks * 8 + tig;
            a[mt][0] = AsU[rb * astride + kb];
            a[mt][1] = AsU[(rb + 8) * astride + kb];
            a[mt][2] = AsU[rb * astride + kb + 4];
            a[mt][3] = AsU[(rb + 8) * astride + kb + 4];
        }
        uint32_t b[8][2];
#pragma unroll
        for (int nt = 0; nt < 8; nt++) {
            const int nb = warp_n * 64 + nt * 8 + grp;
            b[nt][0] = BsU[(ks * 8 + tig) * B_STRIDE + nb];
            b[nt][1] = BsU[(ks * 8 + tig + 4) * B_STRIDE + nb];
        }
#pragma unroll
        for (int mt = 0; mt < 2; mt++)
#pragma unroll
            for (int nt = 0; nt < 8; nt++)
                MMA8(c[mt][nt], a[mt][0], a[mt][1], a[mt][2], a[mt][3],
                     b[nt][0], b[nt][1]);
    }
}

// ============================================================================
// Megakernel. grid = (256 row-blocks, 3 roles), 256 threads, 2 CTAs/SM.
//   y=0: experts 0..4 -> chart        (long CTAs first: better tail packing)
//   y=1: experts 5..9 -> chart
//   y=2: router L1 (2 col tiles) + L2 + logits + gumbel -> wts
// 3-stage cp.async ring, 2 groups in flight, wait_group 1 in mainloops ->
// the awaited chunk was issued 2 chunks earlier (latency fully hidden).
// After its role work each CTA bumps g_cnt[rb]; the 3rd finisher computes z.
// ============================================================================
__global__ __launch_bounds__(256, 2) void mega(
    const float* __restrict__ xt, const float* __restrict__ wr1,
    const float* __restrict__ rb1, const float* __restrict__ wr2,
    const float* __restrict__ rb2, const float* __restrict__ rw3,
    const float* __restrict__ rb3, const float* __restrict__ u,
    const float* __restrict__ we1, const float* __restrict__ eb1,
    const float* __restrict__ we2, const float* __restrict__ eb2,
    const float* __restrict__ ew3, const float* __restrict__ eb3,
    float* __restrict__ hr1, float* __restrict__ wts, float* __restrict__ chart,
    float* __restrict__ z)
{
    extern __shared__ float smf[];
    __shared__ float zcs[256];        // expert L3 reduction [128 rows][2]
    __shared__ float ew3s[256];       // ew3[e] slice [128][2]
    __shared__ float eb1s[128];
    __shared__ float eb2s[128];
    __shared__ int s_old;

    const uint32_t smem_base = s2u(smf);
    const int tid = threadIdx.x;
    const int wid = tid >> 5, lane = tid & 31;
    const int grp = lane >> 2, tig = lane & 3;
    const int warp_m = wid & 3, warp_n = wid >> 2;   // 4 x 2 warps, 32x64 tiles
    const int row0 = blockIdx.x * 128;
    const int role = (blockIdx.y == 2) ? 0 : (int)blockIdx.y + 1;  // experts first

    // cp.async staging maps (256 threads)
    const int arow = tid >> 1, ahalf = tid & 1;     // A: row, float4-half
    const int bkrow = tid >> 3, boct = tid & 7;     // B: k-row, float4-oct

    float c[2][8][4];

    if (role == 0) {
        // ---------------- ROUTER ----------------
        const float* Ag = xt + (long long)(row0 + arow) * DD;

        // --- R1: two 128-col tiles, K=512, 16 chunks, 3-stage ---
        for (int ct = 0; ct < 2; ct++) {
            auto loadR1 = [&](int i) {
                const uint32_t sA = smem_base + (i % 3) * (STG_F * 4);
                const uint32_t sB = sA + A_STG * 4;
#pragma unroll
                for (int j = 0; j < 4; j++) {
                    const int k4 = ahalf * 4 + j;
                    CPA(sA + arow * (A_STRIDE * 4) + k4 * 16, Ag + i * 32 + k4 * 4);
                }
                const float* Wg = wr1 + (long long)(i * 32 + bkrow) * RH1 + ct * 128;
#pragma unroll
                for (int j = 0; j < 4; j++) {
                    const int c4 = boct + j * 8;
                    CPA(sB + bkrow * (B_STRIDE * 4) + c4 * 16, Wg + c4 * 4);
                }
                CPC();
            };
#pragma unroll
            for (int mt = 0; mt < 2; mt++)
#pragma unroll
                for (int nt = 0; nt < 8; nt++)
#pragma unroll
                    for (int q = 0; q < 4; q++) c[mt][nt][q] = 0.f;

            loadR1(0); loadR1(1);
            for (int i = 0; i < 16; i++) {
                if (i + 1 < 16) CPW1(); else CPW0();
                __syncthreads();
                if (i + 2 < 16) loadR1(i + 2);
                const uint32_t* AsU = (const uint32_t*)(smf + (i % 3) * STG_F);
                mma_chunk(AsU, A_STRIDE, AsU + A_STG, c, warp_m, warp_n, grp, tig);
            }

            // epilogue: hr1[:, ct*128 ..] = round(relu(c + rb1))  (registers only)
#pragma unroll
            for (int mt = 0; mt < 2; mt++) {
                const int rb = row0 + warp_m * 32 + mt * 16 + grp;
#pragma unroll
                for (int nt = 0; nt < 8; nt++) {
                    const int col = ct * 128 + warp_n * 64 + nt * 8 + 2 * tig;
                    const float b0 = rb1[col], b1 = rb1[col + 1];
                    const float v0 = tf32r(fmaxf(c[mt][nt][0] + b0, 0.f));
                    const float v1 = tf32r(fmaxf(c[mt][nt][1] + b1, 0.f));
                    const float v2 = tf32r(fmaxf(c[mt][nt][2] + b0, 0.f));
                    const float v3 = tf32r(fmaxf(c[mt][nt][3] + b1, 0.f));
                    *(float2*)(hr1 + (long long)rb * RH1 + col)       = make_float2(v0, v1);
                    *(float2*)(hr1 + (long long)(rb + 8) * RH1 + col) = make_float2(v2, v3);
                }
            }
            __syncthreads();   // ring drained by all warps before reuse / hr1 visible
        }

        // --- R2: K=256, N=128, A = hr1 rows, 8 chunks, 3-stage ---
        const float* Ag2 = hr1 + (long long)(row0 + arow) * RH1;
        auto loadR2 = [&](int i) {
            const uint32_t sA = smem_base + (i % 3) * (STG_F * 4);
            const uint32_t sB = sA + A_STG * 4;
#pragma unroll
            for (int j = 0; j < 4; j++) {
                const int k4 = ahalf * 4 + j;
                CPA(sA + arow * (A_STRIDE * 4) + k4 * 16, Ag2 + i * 32 + k4 * 4);
            }
            const float* Wg = wr2 + (long long)(i * 32 + bkrow) * RH2;
#pragma unroll
            for (int j = 0; j < 4; j++) {
                const int c4 = boct + j * 8;
                CPA(sB + bkrow * (B_STRIDE * 4) + c4 * 16, Wg + c4 * 4);
            }
            CPC();
        };
#pragma unroll
        for (int mt = 0; mt < 2; mt++)
#pragma unroll
            for (int nt = 0; nt < 8; nt++)
#pragma unroll
                for (int q = 0; q < 4; q++) c[mt][nt][q] = 0.f;

        loadR2(0); loadR2(1);
        for (int i = 0; i < 8; i++) {
            if (i + 1 < 8) CPW1(); else CPW0();
            __syncthreads();
            if (i + 2 < 8) loadR2(i + 2);
            const uint32_t* AsU = (const uint32_t*)(smf + (i % 3) * STG_F);
            mma_chunk(AsU, A_STRIDE, AsU + A_STG, c, warp_m, warp_n, grp, tig);
        }
        __syncthreads();   // ring drained; overlay w3s/lgs there

        // --- logits: relu(c + rb2) @ rw3, smem atomics (w3s/lgs overlay stage0) ---
        float* w3s = smf;                   // [RH2][EE]
        float* lgs = smf + RH2 * EE;        // [128][EE]
        for (int i = tid; i < RH2 * EE; i += 256) { w3s[i] = rw3[i]; lgs[i] = 0.f; }
        __syncthreads();

#pragma unroll
        for (int mt = 0; mt < 2; mt++) {
            float pl0[EE], pl1[EE];
#pragma unroll
            for (int e = 0; e < EE; e++) { pl0[e] = 0.f; pl1[e] = 0.f; }
#pragma unroll
            for (int nt = 0; nt < 8; nt++) {
                const int col = warp_n * 64 + nt * 8 + 2 * tig;
                const float b0 = rb2[col], b1 = rb2[col + 1];
                const float v0 = fmaxf(c[mt][nt][0] + b0, 0.f);
                const float v1 = fmaxf(c[mt][nt][1] + b1, 0.f);
                const float v2 = fmaxf(c[mt][nt][2] + b0, 0.f);
                const float v3 = fmaxf(c[mt][nt][3] + b1, 0.f);
#pragma unroll
                for (int e = 0; e < EE; e++) {
                    const float w0 = w3s[col * EE + e], w1 = w3s[(col + 1) * EE + e];
                    pl0[e] += v0 * w0 + v1 * w1;
                    pl1[e] += v2 * w0 + v3 * w1;
                }
            }
            const int r = warp_m * 32 + mt * 16 + grp;
#pragma unroll
            for (int e = 0; e < EE; e++) {
                atomicAdd(&lgs[r * EE + e], pl0[e]);
                atomicAdd(&lgs[(r + 8) * EE + e], pl1[e]);
            }
        }
        __syncthreads();

        // --- gumbel softmax -> wts ---
        if (tid < 128) {
            const long long row = row0 + tid;
            float lg[EE];
            float m = -1e30f;
#pragma unroll
            for (int e = 0; e < EE; e++) {
                float uu = u[row * EE + e];
                uu = fminf(fmaxf(uu, 1e-10f), 1.0f);
                const float g = -logf(-logf(uu) + 1e-10f);
                lg[e] = (lgs[tid * EE + e] + rb3[e] + g) * (1.0f / 3.0f);
                m = fmaxf(m, lg[e]);
            }
            float s = 0.f;
#pragma unroll
            for (int e = 0; e < EE; e++) { lg[e] = expf(lg[e] - m); s += lg[e]; }
            const float inv = 1.0f / s;
#pragma unroll
            for (int e = 0; e < EE; e++) wts[row * EE + e] = lg[e] * inv;
        }
    } else {
        // ---------------- EXPERTS (5 per block) ----------------
        const int e0 = 5 * (role - 1);
        const float* Ag = xt + (long long)(row0 + arow) * DD;

        auto loadL1 = [&](int e, int i) {
            const uint32_t sA = smem_base + (i % 3) * (STG_F * 4);
            const uint32_t sB = sA + A_STG * 4;
#pragma unroll
            for (int j = 0; j < 4; j++) {
                const int k4 = ahalf * 4 + j;
                CPA(sA + arow * (A_STRIDE * 4) + k4 * 16, Ag + i * 32 + k4 * 4);
            }
            const float* Wg = we1 + ((long long)e * DD + i * 32 + bkrow) * HH;
#pragma unroll
            for (int j = 0; j < 4; j++) {
                const int c4 = boct + j * 8;
                CPA(sB + bkrow * (B_STRIDE * 4) + c4 * 16, Wg + c4 * 4);
            }
            CPC();
        };
        auto loadL2B = [&](int e, int kc) {
            const uint32_t sB = smem_base + L2B_OFF * 4 + (kc & 1) * (B_STG * 4);
            const float* Wg = we2 + ((long long)e * HH + kc * 32 + bkrow) * HH;
#pragma unroll
            for (int j = 0; j < 4; j++) {
                const int c4 = boct + j * 8;
                CPA(sB + bkrow * (B_STRIDE * 4) + c4 * 16, Wg + c4 * 4);
            }
            CPC();
        };

        loadL1(e0, 0); loadL1(e0, 1);
        for (int e = e0; e < e0 + 5; e++) {
            if (tid < 128) eb1s[tid] = eb1[e * HH + tid];
#pragma unroll
            for (int mt = 0; mt < 2; mt++)
#pragma unroll
                for (int nt = 0; nt < 8; nt++)
#pragma unroll
                    for (int q = 0; q < 4; q++) c[mt][nt][q] = 0.f;

            // --- L1: K=512, 16 chunks, 3-stage (chunks 0,1 already in flight) ---
            for (int i = 0; i < 16; i++) {
                if (i + 1 < 16) CPW1(); else CPW0();
                __syncthreads();
                if (i + 2 < 16) loadL1(e, i + 2);
                const uint32_t* AsU = (const uint32_t*)(smf + (i % 3) * STG_F);
                mma_chunk(AsU, A_STRIDE, AsU + A_STG, c, warp_m, warp_n, grp, tig);
            }
            loadL2B(e, 0);      // stage-2 region: free (L1 drained)
            __syncthreads();    // ring readers done before h1 overlay write

            // --- h1 = round(relu(c + eb1)) -> smem (overlays stages 0-1) ---
#pragma unroll
            for (int mt = 0; mt < 2; mt++) {
                const int r = warp_m * 32 + mt * 16 + grp;
#pragma unroll
                for (int nt = 0; nt < 8; nt++) {
                    const int col = warp_n * 64 + nt * 8 + 2 * tig;
                    const float b0 = eb1s[col], b1 = eb1s[col + 1];
                    smf[r * H1_STRIDE + col]           = tf32r(fmaxf(c[mt][nt][0] + b0, 0.f));
                    smf[r * H1_STRIDE + col + 1]       = tf32r(fmaxf(c[mt][nt][1] + b1, 0.f));
                    smf[(r + 8) * H1_STRIDE + col]     = tf32r(fmaxf(c[mt][nt][2] + b0, 0.f));
                    smf[(r + 8) * H1_STRIDE + col + 1] = tf32r(fmaxf(c[mt][nt][3] + b1, 0.f));
                }
            }

            // --- L2: K=128, 4 chunks, A from h1 smem, B double-buffered ---
#pragma unroll
            for (int mt = 0; mt < 2; mt++)
#pragma unroll
                for (int nt = 0; nt < 8; nt++)
#pragma unroll
                    for (int q = 0; q < 4; q++) c[mt][nt][q] = 0.f;

            const uint32_t* H1U = (const uint32_t*)smf;
            for (int kc = 0; kc < 4; kc++) {
                CPW0();
                __syncthreads();    // also orders h1 writes before first reads
                if (kc + 1 < 4) loadL2B(e, kc + 1);
                const uint32_t* BsU = (const uint32_t*)(smf + L2B_OFF + (kc & 1) * B_STG);
                mma_chunk(H1U + kc * 32, H1_STRIDE, BsU, c, warp_m, warp_n, grp, tig);
            }
            __syncthreads();        // h1 reads done before ring reuse

            if (e + 1 < e0 + 5) { loadL1(e + 1, 0); loadL1(e + 1, 1); }

            // --- L3: zc = relu(c + eb2) @ ew3[e] -> chart ---
            ew3s[tid] = ew3[(long long)e * 256 + tid];
            if (tid < 128) eb2s[tid] = eb2[e * HH + tid];
            zcs[tid] = 0.f;
            __syncthreads();

#pragma unroll
            for (int mt = 0; mt < 2; mt++) {
                float p00 = 0.f, p01 = 0.f, p10 = 0.f, p11 = 0.f;
#pragma unroll
                for (int nt = 0; nt < 8; nt++) {
                    const int col = warp_n * 64 + nt * 8 + 2 * tig;
                    const float b0 = eb2s[col], b1 = eb2s[col + 1];
                    const float v0 = fmaxf(c[mt][nt][0] + b0, 0.f);
                    const float v1 = fmaxf(c[mt][nt][1] + b1, 0.f);
                    const float v2 = fmaxf(c[mt][nt][2] + b0, 0.f);
                    const float v3 = fmaxf(c[mt][nt][3] + b1, 0.f);
                    const float w00 = ew3s[col * 2],       w01 = ew3s[col * 2 + 1];
                    const float w10 = ew3s[(col + 1) * 2], w11 = ew3s[(col + 1) * 2 + 1];
                    p00 += v0 * w00 + v1 * w10;  p01 += v0 * w01 + v1 * w11;
                    p10 += v2 * w00 + v3 * w10;  p11 += v2 * w01 + v3 * w11;
                }
                const int r = warp_m * 32 + mt * 16 + grp;
                atomicAdd(&zcs[r * 2],           p00);
                atomicAdd(&zcs[r * 2 + 1],       p01);
                atomicAdd(&zcs[(r + 8) * 2],     p10);
                atomicAdd(&zcs[(r + 8) * 2 + 1], p11);
            }
            __syncthreads();

            if (tid < 128) {
                const long long row = row0 + tid;
                const float zc0 = zcs[tid * 2]     + eb3[e * 2];
                const float zc1 = zcs[tid * 2 + 1] + eb3[e * 2 + 1];
                *(float2*)(chart + ((long long)e * BB + row) * 2) = make_float2(zc0, zc1);
            }
            __syncthreads();   // zcs/ew3s/eb1s reuse next expert
        }
    }

    // ---------------- completion: 3rd finisher computes z ----------------
    __threadfence();
    __syncthreads();
    if (tid == 0) s_old = atomicAdd(&g_cnt[blockIdx.x], 1);
    __syncthreads();
    if (s_old == 2) {
        __threadfence();
        if (tid < 128) {
            const long long row = row0 + tid;
            float z0 = 0.f, z1 = 0.f;
#pragma unroll
            for (int e = 0; e < EE; e++) {
                const float w  = __ldcg(&wts[row * EE + e]);
                const float a0 = __ldcg(&chart[((long long)e * BB + row) * 2]);
                const float a1 = __ldcg(&chart[((long long)e * BB + row) * 2 + 1]);
                z0 += w * a0;
                z1 += w * a1;
            }
            *(float2*)(z + row * 2) = make_float2(z0, z1);
        }
    }
}

// ============================================================================
// All operand rounding (rna -> tf32) in one launch; also resets g_cnt.
// ============================================================================
#define S0 (BB * DD / 4)
#define S1 (DD * RH1 / 4)
#define S2 (RH1 * RH2 / 4)
#define S3 (EE * DD * HH / 4)
#define S4 (EE * HH * HH / 4)
#define STOT (S0 + S1 + S2 + S3 + S4)

__global__ __launch_bounds__(256) void round_all(
    const float4* __restrict__ x, const float4* __restrict__ rw1,
    const float4* __restrict__ rw2, const float4* __restrict__ ew1,
    const float4* __restrict__ ew2,
    float4* __restrict__ xt, float4* __restrict__ wr1, float4* __restrict__ wr2,
    float4* __restrict__ we1, float4* __restrict__ we2)
{
    if (blockIdx.x == 0 && threadIdx.x < BB / 128) g_cnt[threadIdx.x] = 0;

    long long i = (long long)blockIdx.x * 256 + threadIdx.x;
    const float4* src; float4* dst; long long off;
    if      (i < S0)                { src = x;   dst = xt;  off = i; }
    else if (i < S0 + S1)           { src = rw1; dst = wr1; off = i - S0; }
    else if (i < S0 + S1 + S2)      { src = rw2; dst = wr2; off = i - S0 - S1; }
    else if (i < S0 + S1 + S2 + S3) { src = ew1; dst = we1; off = i - S0 - S1 - S2; }
    else if (i < STOT)              { src = ew2; dst = we2; off = i - S0 - S1 - S2 - S3; }
    else return;
    float4 v = src[off];
    v.x = tf32r(v.x); v.y = tf32r(v.y); v.z = tf32r(v.z); v.w = tf32r(v.w);
    dst[off] = v;
}

// ============================================================================
extern "C" void kernel_launch(void* const* d_in, const int* in_sizes, int n_in,
                              void* d_out, int out_size)
{
    const float* x   = (const float*)d_in[0];
    const float* u   = (const float*)d_in[1];
    const float* rw1 = (const float*)d_in[2];
    const float* rb1 = (const float*)d_in[3];
    const float* rw2 = (const float*)d_in[4];
    const float* rb2 = (const float*)d_in[5];
    const float* rw3 = (const float*)d_in[6];
    const float* rb3 = (const float*)d_in[7];
    const float* ew1 = (const float*)d_in[8];
    const float* eb1 = (const float*)d_in[9];
    const float* ew2 = (const float*)d_in[10];
    const float* eb2 = (const float*)d_in[11];
    const float* ew3 = (const float*)d_in[12];
    const float* eb3 = (const float*)d_in[13];

    float* out   = (float*)d_out;
    float* z     = out;                                      // [B, 2]
    float* wts   = out + (size_t)BB * 2;                     // [B, E]
    float* chart = out + (size_t)BB * 2 + (size_t)BB * EE;   // [E, B, 2]

    float *hr1, *xt, *wr1, *wr2, *we1, *we2;
    cudaGetSymbolAddress((void**)&hr1, g_hr1);
    cudaGetSymbolAddress((void**)&xt, g_xt);
    cudaGetSymbolAddress((void**)&wr1, g_wr1);
    cudaGetSymbolAddress((void**)&wr2, g_wr2);
    cudaGetSymbolAddress((void**)&we1, g_we1);
    cudaGetSymbolAddress((void**)&we2, g_we2);

    cudaFuncSetAttribute(mega, cudaFuncAttributeMaxDynamicSharedMemorySize, MEGA_SMEM);

    round_all<<<(STOT + 255) / 256, 256>>>(
        (const float4*)x, (const float4*)rw1, (const float4*)rw2,
        (const float4*)ew1, (const float4*)ew2,
        (float4*)xt, (float4*)wr1, (float4*)wr2, (float4*)we1, (float4*)we2);

    mega<<<dim3(BB / 128, 3), 256, MEGA_SMEM>>>(
        xt, wr1, rb1, wr2, rb2, rw3, rb3, u,
        we1, eb1, we2, eb2, ew3, eb3, hr1, wts, chart, z);
}

// round 13
// speedup vs baseline: 2.6461x; 2.6461x over previous
#include <cuda_runtime.h>
#include <cuda_fp16.h>
#include <cstdint>

#define BB 32768
#define DD 512
#define EE 10
#define HH 128
#define RH1 256
#define RH2 128

// ---- packed fp16 scratch (static __device__ globals: allocation-guard safe) ----
// Packing: u32 = half2(v[2k], v[2k+1]) along the K (contraction) dimension.
__device__ uint32_t g_xtp[(size_t)BB * (DD / 2)];        // x packed   [B][256]
__device__ uint32_t g_hr1p[(size_t)BB * (RH1 / 2)];      // hr1 packed [B][128]
__device__ uint32_t g_w1p[(size_t)(DD / 2) * RH1];       // rw1 packed [256][256]
__device__ uint32_t g_w2p[(size_t)(RH1 / 2) * RH2];      // rw2 packed [128][128]
__device__ uint32_t g_e1p[(size_t)EE * (DD / 2) * HH];   // we1 packed [10*256][128]
__device__ uint32_t g_e2p[(size_t)EE * (HH / 2) * HH];   // we2 packed [10*64][128]
__device__ int      g_cnt[BB / 128];                     // completion counters

__device__ __forceinline__ uint32_t pkh2(float a, float b) {
    __half2 h = __floats2half2_rn(a, b);
    return *reinterpret_cast<uint32_t*>(&h);
}
__device__ __forceinline__ uint32_t s2u(const void* p) {
    uint32_t a;
    asm("{ .reg .u64 t; cvta.to.shared.u64 t, %1; cvt.u32.u64 %0, t; }" : "=r"(a) : "l"(p));
    return a;
}

// ---- smem geometry (u32 units). Conflict-free strides mod 32: 36->4, 136->8, 68->4.
#define A_STRIDE 36                        // A tile: 128 rows x 32 u32 (=64 fp16 k)
#define B_STRIDE 136                       // B tile: 32 kp-rows x 128 u32 (n cols)
#define A_STG (128 * A_STRIDE)             // 4608 u32
#define B_STG (32 * B_STRIDE)              // 4352 u32
#define STG_F (A_STG + B_STG)              // 8960 u32 per stage
#define AUX_OFF (2 * STG_F)                // expert L2-B double buffer
#define H1_STRIDE 68                       // h1 packed buffer: 128 rows x 64 u32
#define MEGA_SMEM ((AUX_OFF + 2 * B_STG) * 4)   // 106496 B -> 2 CTAs/SM (proven)

#define CPA(dst, src) \
    asm volatile("cp.async.cg.shared.global [%0], [%1], 16;" :: "r"(dst), "l"(src) : "memory")
#define CPC() asm volatile("cp.async.commit_group;" ::: "memory")
#define CPW0() asm volatile("cp.async.wait_group 0;" ::: "memory")

#define MMA16(cc, a0, a1, a2, a3, b0, b1) \
    asm volatile("mma.sync.aligned.m16n8k16.row.col.f32.f16.f16.f32 " \
                 "{%0,%1,%2,%3}, {%4,%5,%6,%7}, {%8,%9}, {%0,%1,%2,%3};" \
                 : "+f"(cc[0]), "+f"(cc[1]), "+f"(cc[2]), "+f"(cc[3]) \
                 : "r"(a0), "r"(a1), "r"(a2), "r"(a3), "r"(b0), "r"(b1))

// One 64-k chunk (4 x k16 steps) of 128x128 CTA-tile MMA work. 8 warps
// (4m x 2n), warp tile 32x64. AsU: packed A rows (stride astride, u32 kp idx
// 0..31); BsU: packed B kp-rows (stride B_STRIDE, n cols 0..127).
__device__ __forceinline__ void mma_chunk(
    const uint32_t* __restrict__ AsU, int astride,
    const uint32_t* __restrict__ BsU,
    float (&c)[2][8][4], int warp_m, int warp_n, int grp, int tig)
{
#pragma unroll
    for (int s = 0; s < 4; s++) {
        uint32_t a[2][4];
#pragma unroll
        for (int mt = 0; mt < 2; mt++) {
            const int rb = warp_m * 32 + mt * 16 + grp;
            const int kp = s * 8 + tig;
            a[mt][0] = AsU[rb * astride + kp];
            a[mt][1] = AsU[(rb + 8) * astride + kp];
            a[mt][2] = AsU[rb * astride + kp + 4];
            a[mt][3] = AsU[(rb + 8) * astride + kp + 4];
        }
        uint32_t b[8][2];
#pragma unroll
        for (int nt = 0; nt < 8; nt++) {
            const int nb = warp_n * 64 + nt * 8 + grp;
            b[nt][0] = BsU[(s * 8 + tig) * B_STRIDE + nb];
            b[nt][1] = BsU[(s * 8 + tig + 4) * B_STRIDE + nb];
        }
#pragma unroll
        for (int mt = 0; mt < 2; mt++)
#pragma unroll
            for (int nt = 0; nt < 8; nt++)
                MMA16(c[mt][nt], a[mt][0], a[mt][1], a[mt][2], a[mt][3],
                      b[nt][0], b[nt][1]);
    }
}

// ============================================================================
// Megakernel (R11 structure, fp16 k16 math). grid = (256 row-blocks, 3 roles),
// 256 threads, 2 CTAs/SM, 2-stage cp.async ring with CPW0 (proven optimum).
//   y=0: experts 0..4 -> chart    y=1: experts 5..9 -> chart
//   y=2: router L1 (2 col tiles) + L2 + logits + gumbel -> wts
// 3rd finisher per row-block computes z.
// ============================================================================
__global__ __launch_bounds__(256, 2) void mega(
    const uint32_t* __restrict__ xtp, const uint32_t* __restrict__ w1p,
    const float* __restrict__ rb1, const uint32_t* __restrict__ w2p,
    const float* __restrict__ rb2, const float* __restrict__ rw3,
    const float* __restrict__ rb3, const float* __restrict__ u,
    const uint32_t* __restrict__ e1p, const float* __restrict__ eb1,
    const uint32_t* __restrict__ e2p, const float* __restrict__ eb2,
    const float* __restrict__ ew3, const float* __restrict__ eb3,
    uint32_t* __restrict__ hr1p, float* __restrict__ wts,
    float* __restrict__ chart, float* __restrict__ z)
{
    extern __shared__ uint32_t smu[];
    __shared__ float zcs[256];
    __shared__ float ew3s[256];
    __shared__ float eb1s[128];
    __shared__ float eb2s[128];
    __shared__ int s_old;

    const uint32_t smem_base = s2u(smu);
    const int tid = threadIdx.x;
    const int wid = tid >> 5, lane = tid & 31;
    const int grp = lane >> 2, tig = lane & 3;
    const int warp_m = wid & 3, warp_n = wid >> 2;   // 4 x 2 warps, 32x64 tiles
    const int row0 = blockIdx.x * 128;
    const int role = (blockIdx.y == 2) ? 0 : (int)blockIdx.y + 1;  // experts first

    // cp.async staging maps (256 threads); byte geometry identical to R11:
    // A chunk: 128 rows x 128B; B chunk: 32 rows x 512B.
    const int arow = tid >> 1, ahalf = tid & 1;     // A: row, 4x16B per thread
    const int bkrow = tid >> 3, boct = tid & 7;     // B: kp-row, 4x16B per thread

    float c[2][8][4];

    if (role == 0) {
        // ---------------- ROUTER ----------------
        const uint32_t* Ag = xtp + (long long)(row0 + arow) * (DD / 2);

        // --- R1: two 128-col tiles, K=512 -> 8 chunks of 64k ---
        for (int ct = 0; ct < 2; ct++) {
            auto loadR1 = [&](int i) {
                const uint32_t sA = smem_base + (i & 1) * (STG_F * 4);
                const uint32_t sB = sA + A_STG * 4;
#pragma unroll
                for (int j = 0; j < 4; j++) {
                    const int k4 = ahalf * 4 + j;
                    CPA(sA + arow * (A_STRIDE * 4) + k4 * 16, Ag + i * 32 + k4 * 4);
                }
                const uint32_t* Wg = w1p + (long long)(i * 32 + bkrow) * RH1 + ct * 128;
#pragma unroll
                for (int j = 0; j < 4; j++) {
                    const int c4 = boct + j * 8;
                    CPA(sB + bkrow * (B_STRIDE * 4) + c4 * 16, Wg + c4 * 4);
                }
                CPC();
            };
#pragma unroll
            for (int mt = 0; mt < 2; mt++)
#pragma unroll
                for (int nt = 0; nt < 8; nt++)
#pragma unroll
                    for (int q = 0; q < 4; q++) c[mt][nt][q] = 0.f;

            loadR1(0);
            for (int i = 0; i < 8; i++) {
                CPW0();
                __syncthreads();
                if (i + 1 < 8) loadR1(i + 1);
                const uint32_t* AsU = smu + (i & 1) * STG_F;
                mma_chunk(AsU, A_STRIDE, AsU + A_STG, c, warp_m, warp_n, grp, tig);
            }

            // epilogue: hr1p[:, ct half] = pack(relu(c + rb1))
#pragma unroll
            for (int mt = 0; mt < 2; mt++) {
                const int rb = row0 + warp_m * 32 + mt * 16 + grp;
#pragma unroll
                for (int nt = 0; nt < 8; nt++) {
                    const int col = warp_n * 64 + nt * 8 + 2 * tig;   // 0..127 in ct
                    const int colp = ct * 64 + (col >> 1);
                    const float b0 = rb1[ct * 128 + col], b1 = rb1[ct * 128 + col + 1];
                    const float v0 = fmaxf(c[mt][nt][0] + b0, 0.f);
                    const float v1 = fmaxf(c[mt][nt][1] + b1, 0.f);
                    const float v2 = fmaxf(c[mt][nt][2] + b0, 0.f);
                    const float v3 = fmaxf(c[mt][nt][3] + b1, 0.f);
                    hr1p[(long long)rb * (RH1 / 2) + colp]       = pkh2(v0, v1);
                    hr1p[(long long)(rb + 8) * (RH1 / 2) + colp] = pkh2(v2, v3);
                }
            }
            __syncthreads();   // ring drained before next ct / R2
        }

        // --- R2: K=256 -> 4 chunks, A = hr1p rows ---
        const uint32_t* Ag2 = hr1p + (long long)(row0 + arow) * (RH1 / 2);
        auto loadR2 = [&](int i) {
            const uint32_t sA = smem_base + (i & 1) * (STG_F * 4);
            const uint32_t sB = sA + A_STG * 4;
#pragma unroll
            for (int j = 0; j < 4; j++) {
                const int k4 = ahalf * 4 + j;
                CPA(sA + arow * (A_STRIDE * 4) + k4 * 16, Ag2 + i * 32 + k4 * 4);
            }
            const uint32_t* Wg = w2p + (long long)(i * 32 + bkrow) * RH2;
#pragma unroll
            for (int j = 0; j < 4; j++) {
                const int c4 = boct + j * 8;
                CPA(sB + bkrow * (B_STRIDE * 4) + c4 * 16, Wg + c4 * 4);
            }
            CPC();
        };
#pragma unroll
        for (int mt = 0; mt < 2; mt++)
#pragma unroll
            for (int nt = 0; nt < 8; nt++)
#pragma unroll
                for (int q = 0; q < 4; q++) c[mt][nt][q] = 0.f;

        loadR2(0);
        for (int i = 0; i < 4; i++) {
            CPW0();
            __syncthreads();
            if (i + 1 < 4) loadR2(i + 1);
            const uint32_t* AsU = smu + (i & 1) * STG_F;
            mma_chunk(AsU, A_STRIDE, AsU + A_STG, c, warp_m, warp_n, grp, tig);
        }
        __syncthreads();   // ring drained; overlay w3s/lgs there

        // --- logits: relu(c + rb2) @ rw3, smem atomics ---
        float* w3s = (float*)smu;                   // [RH2][EE]
        float* lgs = (float*)smu + RH2 * EE;        // [128][EE]
        for (int i = tid; i < RH2 * EE; i += 256) { w3s[i] = rw3[i]; lgs[i] = 0.f; }
        __syncthreads();

#pragma unroll
        for (int mt = 0; mt < 2; mt++) {
            float pl0[EE], pl1[EE];
#pragma unroll
            for (int e = 0; e < EE; e++) { pl0[e] = 0.f; pl1[e] = 0.f; }
#pragma unroll
            for (int nt = 0; nt < 8; nt++) {
                const int col = warp_n * 64 + nt * 8 + 2 * tig;
                const float b0 = rb2[col], b1 = rb2[col + 1];
                const float v0 = fmaxf(c[mt][nt][0] + b0, 0.f);
                const float v1 = fmaxf(c[mt][nt][1] + b1, 0.f);
                const float v2 = fmaxf(c[mt][nt][2] + b0, 0.f);
                const float v3 = fmaxf(c[mt][nt][3] + b1, 0.f);
#pragma unroll
                for (int e = 0; e < EE; e++) {
                    const float w0 = w3s[col * EE + e], w1 = w3s[(col + 1) * EE + e];
                    pl0[e] += v0 * w0 + v1 * w1;
                    pl1[e] += v2 * w0 + v3 * w1;
                }
            }
            const int r = warp_m * 32 + mt * 16 + grp;
#pragma unroll
            for (int e = 0; e < EE; e++) {
                atomicAdd(&lgs[r * EE + e], pl0[e]);
                atomicAdd(&lgs[(r + 8) * EE + e], pl1[e]);
            }
        }
        __syncthreads();

        // --- gumbel softmax -> wts ---
        if (tid < 128) {
            const long long row = row0 + tid;
            float lg[EE];
            float m = -1e30f;
#pragma unroll
            for (int e = 0; e < EE; e++) {
                float uu = u[row * EE + e];
                uu = fminf(fmaxf(uu, 1e-10f), 1.0f);
                const float g = -logf(-logf(uu) + 1e-10f);
                lg[e] = (lgs[tid * EE + e] + rb3[e] + g) * (1.0f / 3.0f);
                m = fmaxf(m, lg[e]);
            }
            float s = 0.f;
#pragma unroll
            for (int e = 0; e < EE; e++) { lg[e] = expf(lg[e] - m); s += lg[e]; }
            const float inv = 1.0f / s;
#pragma unroll
            for (int e = 0; e < EE; e++) wts[row * EE + e] = lg[e] * inv;
        }
    } else {
        // ---------------- EXPERTS (5 per block) ----------------
        const int e0 = 5 * (role - 1);
        const uint32_t* Ag = xtp + (long long)(row0 + arow) * (DD / 2);

        auto loadL1 = [&](int e, int i) {
            const uint32_t sA = smem_base + (i & 1) * (STG_F * 4);
            const uint32_t sB = sA + A_STG * 4;
#pragma unroll
            for (int j = 0; j < 4; j++) {
                const int k4 = ahalf * 4 + j;
                CPA(sA + arow * (A_STRIDE * 4) + k4 * 16, Ag + i * 32 + k4 * 4);
            }
            const uint32_t* Wg = e1p + ((long long)e * (DD / 2) + i * 32 + bkrow) * HH;
#pragma unroll
            for (int j = 0; j < 4; j++) {
                const int c4 = boct + j * 8;
                CPA(sB + bkrow * (B_STRIDE * 4) + c4 * 16, Wg + c4 * 4);
            }
            CPC();
        };
        auto loadL2B = [&](int e, int kc) {
            const uint32_t sB = smem_base + AUX_OFF * 4 + (kc & 1) * (B_STG * 4);
            const uint32_t* Wg = e2p + ((long long)e * (HH / 2) + kc * 32 + bkrow) * HH;
#pragma unroll
            for (int j = 0; j < 4; j++) {
                const int c4 = boct + j * 8;
                CPA(sB + bkrow * (B_STRIDE * 4) + c4 * 16, Wg + c4 * 4);
            }
            CPC();
        };

        loadL1(e0, 0);
        for (int e = e0; e < e0 + 5; e++) {
            if (tid < 128) eb1s[tid] = eb1[e * HH + tid];
#pragma unroll
            for (int mt = 0; mt < 2; mt++)
#pragma unroll
                for (int nt = 0; nt < 8; nt++)
#pragma unroll
                    for (int q = 0; q < 4; q++) c[mt][nt][q] = 0.f;

            // --- L1: K=512 -> 8 chunks of 64k ---
            for (int i = 0; i < 8; i++) {
                CPW0();
                __syncthreads();
                if (i + 1 < 8) loadL1(e, i + 1);
                const uint32_t* AsU = smu + (i & 1) * STG_F;
                mma_chunk(AsU, A_STRIDE, AsU + A_STG, c, warp_m, warp_n, grp, tig);
            }
            loadL2B(e, 0);      // AUX region: disjoint, safe to start now

            // --- h1 packed -> smem (region = 128 x 68 u32, fits in stage 0;
            //     stage 0 last read by chunk 6, globally synced at i=7 bar) ---
#pragma unroll
            for (int mt = 0; mt < 2; mt++) {
                const int r = warp_m * 32 + mt * 16 + grp;
#pragma unroll
                for (int nt = 0; nt < 8; nt++) {
                    const int col = warp_n * 64 + nt * 8 + 2 * tig;
                    const int colp = col >> 1;
                    const float b0 = eb1s[col], b1 = eb1s[col + 1];
                    const float v0 = fmaxf(c[mt][nt][0] + b0, 0.f);
                    const float v1 = fmaxf(c[mt][nt][1] + b1, 0.f);
                    const float v2 = fmaxf(c[mt][nt][2] + b0, 0.f);
                    const float v3 = fmaxf(c[mt][nt][3] + b1, 0.f);
                    smu[r * H1_STRIDE + colp]       = pkh2(v0, v1);
                    smu[(r + 8) * H1_STRIDE + colp] = pkh2(v2, v3);
                }
            }

            // --- L2: K=128 -> 2 chunks, A from h1 smem, B double-buffered ---
#pragma unroll
            for (int mt = 0; mt < 2; mt++)
#pragma unroll
                for (int nt = 0; nt < 8; nt++)
#pragma unroll
                    for (int q = 0; q < 4; q++) c[mt][nt][q] = 0.f;

            for (int kc = 0; kc < 2; kc++) {
                CPW0();
                __syncthreads();    // kc=0: orders h1 writes before reads
                if (kc + 1 < 2) loadL2B(e, kc + 1);
                const uint32_t* BsU = smu + AUX_OFF + (kc & 1) * B_STG;
                mma_chunk(smu + kc * 32, H1_STRIDE, BsU, c, warp_m, warp_n, grp, tig);
            }
            __syncthreads();        // h1 reads done before stage-0 reuse

            if (e + 1 < e0 + 5) loadL1(e + 1, 0);

            // --- L3: zc = relu(c + eb2) @ ew3[e] -> chart ---
            ew3s[tid] = ew3[(long long)e * 256 + tid];
            if (tid < 128) eb2s[tid] = eb2[e * HH + tid];
            zcs[tid] = 0.f;
            __syncthreads();

#pragma unroll
            for (int mt = 0; mt < 2; mt++) {
                float p00 = 0.f, p01 = 0.f, p10 = 0.f, p11 = 0.f;
#pragma unroll
                for (int nt = 0; nt < 8; nt++) {
                    const int col = warp_n * 64 + nt * 8 + 2 * tig;
                    const float b0 = eb2s[col], b1 = eb2s[col + 1];
                    const float v0 = fmaxf(c[mt][nt][0] + b0, 0.f);
                    const float v1 = fmaxf(c[mt][nt][1] + b1, 0.f);
                    const float v2 = fmaxf(c[mt][nt][2] + b0, 0.f);
                    const float v3 = fmaxf(c[mt][nt][3] + b1, 0.f);
                    const float w00 = ew3s[col * 2],       w01 = ew3s[col * 2 + 1];
                    const float w10 = ew3s[(col + 1) * 2], w11 = ew3s[(col + 1) * 2 + 1];
                    p00 += v0 * w00 + v1 * w10;  p01 += v0 * w01 + v1 * w11;
                    p10 += v2 * w00 + v3 * w10;  p11 += v2 * w01 + v3 * w11;
                }
                const int r = warp_m * 32 + mt * 16 + grp;
                atomicAdd(&zcs[r * 2],           p00);
                atomicAdd(&zcs[r * 2 + 1],       p01);
                atomicAdd(&zcs[(r + 8) * 2],     p10);
                atomicAdd(&zcs[(r + 8) * 2 + 1], p11);
            }
            __syncthreads();

            if (tid < 128) {
                const long long row = row0 + tid;
                const float zc0 = zcs[tid * 2]     + eb3[e * 2];
                const float zc1 = zcs[tid * 2 + 1] + eb3[e * 2 + 1];
                *(float2*)(chart + ((long long)e * BB + row) * 2) = make_float2(zc0, zc1);
            }
            __syncthreads();   // zcs/ew3s/eb1s reuse next expert
        }
    }

    // ---------------- completion: 3rd finisher computes z ----------------
    __threadfence();
    __syncthreads();
    if (tid == 0) s_old = atomicAdd(&g_cnt[blockIdx.x], 1);
    __syncthreads();
    if (s_old == 2) {
        __threadfence();
        if (tid < 128) {
            const long long row = row0 + tid;
            float z0 = 0.f, z1 = 0.f;
#pragma unroll
            for (int e = 0; e < EE; e++) {
                const float w  = __ldcg(&wts[row * EE + e]);
                const float a0 = __ldcg(&chart[((long long)e * BB + row) * 2]);
                const float a1 = __ldcg(&chart[((long long)e * BB + row) * 2 + 1]);
                z0 += w * a0;
                z1 += w * a1;
            }
            *(float2*)(z + row * 2) = make_float2(z0, z1);
        }
    }
}

// ============================================================================
// Convert + k-pairwise pack all GEMM operands to fp16 (rn); reset g_cnt.
// One u32 output per thread.
// ============================================================================
#define XN  (BB * (DD / 2))                 // 8388608
#define W1N ((DD / 2) * RH1)                // 65536
#define W2N ((RH1 / 2) * RH2)               // 16384
#define E1N (EE * (DD / 2) * HH)            // 327680
#define E2N (EE * (HH / 2) * HH)            // 81920
#define TOTN (XN + W1N + W2N + E1N + E2N)   // 8880128

__global__ __launch_bounds__(256) void cvt_all(
    const float2* __restrict__ x2, const float* __restrict__ rw1,
    const float* __restrict__ rw2, const float* __restrict__ ew1,
    const float* __restrict__ ew2,
    uint32_t* __restrict__ xtp, uint32_t* __restrict__ w1p,
    uint32_t* __restrict__ w2p, uint32_t* __restrict__ e1p,
    uint32_t* __restrict__ e2p)
{
    if (blockIdx.x == 0 && threadIdx.x < BB / 128) g_cnt[threadIdx.x] = 0;

    long long i = (long long)blockIdx.x * 256 + threadIdx.x;
    if (i < XN) { const float2 v = x2[i]; xtp[i] = pkh2(v.x, v.y); return; }
    i -= XN;
    if (i < W1N) {
        const int kp = (int)(i >> 8), n = (int)(i & 255);
        w1p[i] = pkh2(rw1[(2 * kp) * RH1 + n], rw1[(2 * kp + 1) * RH1 + n]);
        return;
    }
    i -= W1N;
    if (i < W2N) {
        const int kp = (int)(i >> 7), n = (int)(i & 127);
        w2p[i] = pkh2(rw2[(2 * kp) * RH2 + n], rw2[(2 * kp + 1) * RH2 + n]);
        return;
    }
    i -= W2N;
    if (i < E1N) {   // flat kp across experts (512 rows/expert: even, no straddle)
        const long long kp = i >> 7; const int n = (int)(i & 127);
        e1p[i] = pkh2(ew1[(2 * kp) * HH + n], ew1[(2 * kp + 1) * HH + n]);
        return;
    }
    i -= E1N;
    if (i < E2N) {
        const long long kp = i >> 7; const int n = (int)(i & 127);
        e2p[i] = pkh2(ew2[(2 * kp) * HH + n], ew2[(2 * kp + 1) * HH + n]);
    }
}

// ============================================================================
extern "C" void kernel_launch(void* const* d_in, const int* in_sizes, int n_in,
                              void* d_out, int out_size)
{
    const float* x   = (const float*)d_in[0];
    const float* u   = (const float*)d_in[1];
    const float* rw1 = (const float*)d_in[2];
    const float* rb1 = (const float*)d_in[3];
    const float* rw2 = (const float*)d_in[4];
    const float* rb2 = (const float*)d_in[5];
    const float* rw3 = (const float*)d_in[6];
    const float* rb3 = (const float*)d_in[7];
    const float* ew1 = (const float*)d_in[8];
    const float* eb1 = (const float*)d_in[9];
    const float* ew2 = (const float*)d_in[10];
    const float* eb2 = (const float*)d_in[11];
    const float* ew3 = (const float*)d_in[12];
    const float* eb3 = (const float*)d_in[13];

    float* out   = (float*)d_out;
    float* z     = out;                                      // [B, 2]
    float* wts   = out + (size_t)BB * 2;                     // [B, E]
    float* chart = out + (size_t)BB * 2 + (size_t)BB * EE;   // [E, B, 2]

    uint32_t *xtp, *hr1p, *w1p, *w2p, *e1p, *e2p;
    cudaGetSymbolAddress((void**)&xtp, g_xtp);
    cudaGetSymbolAddress((void**)&hr1p, g_hr1p);
    cudaGetSymbolAddress((void**)&w1p, g_w1p);
    cudaGetSymbolAddress((void**)&w2p, g_w2p);
    cudaGetSymbolAddress((void**)&e1p, g_e1p);
    cudaGetSymbolAddress((void**)&e2p, g_e2p);

    cudaFuncSetAttribute(mega, cudaFuncAttributeMaxDynamicSharedMemorySize, MEGA_SMEM);

    cvt_all<<<TOTN / 256, 256>>>(
        (const float2*)x, rw1, rw2, ew1, ew2, xtp, w1p, w2p, e1p, e2p);

    mega<<<dim3(BB / 128, 3), 256, MEGA_SMEM>>>(
        xtp, w1p, rb1, w2p, rb2, rw3, rb3, u,
        e1p, eb1, e2p, eb2, ew3, eb3, hr1p, wts, chart, z);
}